// round 12
// baseline (speedup 1.0000x reference)
#include <cuda_runtime.h>
#include <cuda_bf16.h>
#include <math.h>
#include <stdint.h>

// Problem constants (B=2, S=2048 -> N=4096 tokens; D=2048; V=32000)
#define NTOK 4096
#define DIM  2048
#define VOC  32000

// Fused GEMM tile config: occupancy-2 variant.
// CTA: z AND m for BMT tokens x BN vocab cols, 256 threads, 3 stages.
#define BMT 64                 // tokens per CTA (both streams)
#define BN 128
#define BK 64                  // bf16 elems per K-chunk (128B = SW128 atom row)
#define KCH (DIM / BK)         // 32
#define STAGES 3
#define ASTG (128 * BK * 2)    // 2 streams x 64 rows x 128B = 16384 B
#define BSTG (BN * BK * 2)     // 16384 B
#define STG (ASTG + BSTG)      // 32768 B
#define SMEM_TOTAL (STAGES * STG + 1024)   // ~99 KB -> 2 CTAs/SM
#define NBV (VOC / BN)         // 250 vocab blocks

// ---- scratch (allocation-free: __device__ globals) ----
__device__ __align__(128) __nv_bfloat16 g_Wb[(size_t)VOC * DIM];        // 131 MB
__device__ __align__(128) __nv_bfloat16 g_Ab[(size_t)2 * NTOK * DIM];   // 33.5 MB
// per-(token, vocab-block) partials
__device__ float g_pSz[NTOK * NBV];
__device__ float g_pSm[NTOK * NBV];
__device__ float g_pT [NTOK * NBV];
__device__ float g_pVz[NTOK * NBV];
__device__ float g_pVm[NTOK * NBV];
__device__ int   g_pIz[NTOK * NBV];
__device__ int   g_pIm[NTOK * NBV];
__device__ float g_zt[NTOK];   // target logit (z stream)
__device__ float g_mt[NTOK];   // target logit (m stream)
__device__ float g_tok[NTOK * 5];

// ============================================================
// 1) fp32 -> bf16 conversion (8 floats / thread)
// ============================================================
__global__ void cvt_all(const float* __restrict__ h,
                        const float* __restrict__ mh,
                        const float* __restrict__ W) {
    const int nW8 = VOC * DIM / 8;       // 8,192,000
    const int nA8 = NTOK * DIM / 8;      // 1,048,576
    int i = blockIdx.x * blockDim.x + threadIdx.x;
    const float4* src;
    uint4* dst;
    int j;
    if (i < nW8) {
        src = (const float4*)W; dst = (uint4*)g_Wb; j = i;
    } else if (i < nW8 + nA8) {
        src = (const float4*)h; dst = (uint4*)g_Ab; j = i - nW8;
    } else if (i < nW8 + 2 * nA8) {
        src = (const float4*)mh;
        dst = (uint4*)(g_Ab + (size_t)NTOK * DIM);
        j = i - nW8 - nA8;
    } else {
        return;
    }
    float4 v0 = src[2 * j];
    float4 v1 = src[2 * j + 1];
    __nv_bfloat162 b0 = __floats2bfloat162_rn(v0.x, v0.y);
    __nv_bfloat162 b1 = __floats2bfloat162_rn(v0.z, v0.w);
    __nv_bfloat162 b2 = __floats2bfloat162_rn(v1.x, v1.y);
    __nv_bfloat162 b3 = __floats2bfloat162_rn(v1.z, v1.w);
    uint4 o;
    o.x = *reinterpret_cast<uint32_t*>(&b0);
    o.y = *reinterpret_cast<uint32_t*>(&b1);
    o.z = *reinterpret_cast<uint32_t*>(&b2);
    o.w = *reinterpret_cast<uint32_t*>(&b3);
    dst[j] = o;
}

// ============================================================
// helpers
// ============================================================
static __device__ __forceinline__ uint32_t smem_u32(const void* p) {
    return (uint32_t)__cvta_generic_to_shared(p);
}
static __device__ __forceinline__ void cp16(uint32_t s, const void* g) {
    asm volatile("cp.async.cg.shared.global [%0], [%1], 16;" :: "r"(s), "l"(g));
}
static __device__ __forceinline__ void cp_commit() {
    asm volatile("cp.async.commit_group;" ::: "memory");
}
template <int N>
static __device__ __forceinline__ void cp_wait() {
    asm volatile("cp.async.wait_group %0;" :: "n"(N) : "memory");
}
#define SW128(o) ((o) ^ (((o) >> 3) & 0x70))

// Robust target read (int64 vs int32 autodetect, never OOB)
__device__ __forceinline__ long long read_target(const int* p, int n) {
    int w1 = p[1], w3 = p[3], w5 = p[5], w7 = p[7];
    bool is64 = ((w1 == 0 || w1 == -1) && (w3 == 0 || w3 == -1) &&
                 (w5 == 0 || w5 == -1) && (w7 == 0 || w7 == -1));
    if (is64) {
        long long lo = (unsigned int)p[2 * n];
        long long hi = p[2 * n + 1];
        return (hi << 32) | lo;
    }
    return (long long)p[n];
}

// ============================================================
// 2) FUSED GEMM + softmax statistics, 2 CTAs/SM.
//    CTA: z and m for 64 tokens x 128 vocab cols; 8 warps = 2M x 4N.
//    Mainloop: kstep0 -> A-half of next-chunk loads -> kstep1 ->
//    B-half -> commit -> ksteps 2,3 (load issue spread across drains).
// ============================================================
__global__ void __launch_bounds__(256, 2) gemm_fused(const int* __restrict__ tgt) {
    extern __shared__ __align__(16) char dyn[];
    __shared__ int   sTgt[BMT];
    __shared__ float pSz[BMT][4], pSm[BMT][4], pT[BMT][4];
    __shared__ float pVz[BMT][4], pVm[BMT][4];
    __shared__ int   pIz[BMT][4], pIm[BMT][4];

    const int bT = blockIdx.x, bV = blockIdx.y;
    const int tid = threadIdx.x, wid = tid >> 5, lane = tid & 31;
    const int wm = (wid & 1) * 32;    // token offset within CTA (2 groups)
    const int wnG = wid >> 1;         // N group 0..3
    const int wn = wnG * 32;
    const int tok0 = bT * BMT;

    uint32_t base = smem_u32(dyn);
    base = (base + 1023u) & ~1023u;

    const __nv_bfloat16* __restrict__ Agz = g_Ab + (size_t)tok0 * DIM;
    const __nv_bfloat16* __restrict__ Agm =
        g_Ab + (size_t)NTOK * DIM + (size_t)tok0 * DIM;
    const __nv_bfloat16* __restrict__ Bg = g_Wb + (size_t)(bV * BN) * DIM;

    if (tid < BMT) {
        long long t = read_target(tgt, tok0 + tid);
        int ti = (t != -100LL) ? (int)t : 0;
        sTgt[tid] = min(max(ti, 0), VOC - 1);
    }

    float acc[2][2][4][4];
    #pragma unroll
    for (int s = 0; s < 2; s++)
        #pragma unroll
        for (int i = 0; i < 2; i++)
            #pragma unroll
            for (int j = 0; j < 4; j++)
                #pragma unroll
                for (int k = 0; k < 4; k++) acc[s][i][j][k] = 0.f;

    // A half of a chunk load (4 x 16B per thread)
    auto load_A = [&](int ci, int st) {
        uint32_t As = base + st * STG;
        #pragma unroll
        for (int r = 0; r < 4; r++) {           // A: 128 rows x 8 segs
            int idx = tid + r * 256;
            int row = idx >> 3, seg = idx & 7;
            const __nv_bfloat16* src = (row < 64)
                ? Agz + (size_t)row * DIM + ci * BK + seg * 8
                : Agm + (size_t)(row - 64) * DIM + ci * BK + seg * 8;
            uint32_t off = (uint32_t)(row * 128 + seg * 16);
            cp16(As + SW128(off), src);
        }
    };
    // B half of a chunk load (4 x 16B per thread)
    auto load_B = [&](int ci, int st) {
        uint32_t Bs = base + st * STG + ASTG;
        #pragma unroll
        for (int r = 0; r < 4; r++) {           // B: 128 rows x 8 segs
            int idx = tid + r * 256;
            int row = idx >> 3, seg = idx & 7;
            uint32_t off = (uint32_t)(row * 128 + seg * 16);
            cp16(Bs + SW128(off), Bg + (size_t)row * DIM + ci * BK + seg * 8);
        }
    };

    // one K=16 sub-step: B frags (2 x ldmatrix.x4), per-stream A frags + HMMA
    auto do_kstep = [&](uint32_t As, uint32_t Bs, int kb) {
        uint32_t b[4][2];
        #pragma unroll
        for (int p = 0; p < 2; p++) {
            int row = wn + p * 16 + ((lane >> 4) & 1) * 8 + (lane & 7);
            uint32_t off = (uint32_t)(row * 128 + kb + ((lane >> 3) & 1) * 16);
            uint32_t sb = Bs + SW128(off);
            asm volatile(
                "ldmatrix.sync.aligned.m8n8.x4.shared.b16 {%0,%1,%2,%3}, [%4];"
                : "=r"(b[2 * p][0]), "=r"(b[2 * p][1]),
                  "=r"(b[2 * p + 1][0]), "=r"(b[2 * p + 1][1])
                : "r"(sb));
        }
        #pragma unroll
        for (int s = 0; s < 2; s++) {
            uint32_t a[2][4];
            #pragma unroll
            for (int mi = 0; mi < 2; mi++) {
                int row = s * 64 + wm + mi * 16
                        + ((lane >> 3) & 1) * 8 + (lane & 7);
                uint32_t off = (uint32_t)(row * 128 + kb + (lane >> 4) * 16);
                uint32_t sa = As + SW128(off);
                asm volatile(
                    "ldmatrix.sync.aligned.m8n8.x4.shared.b16 {%0,%1,%2,%3}, [%4];"
                    : "=r"(a[mi][0]), "=r"(a[mi][1]),
                      "=r"(a[mi][2]), "=r"(a[mi][3])
                    : "r"(sa));
            }
            #pragma unroll
            for (int mi = 0; mi < 2; mi++)
                #pragma unroll
                for (int nj = 0; nj < 4; nj++) {
                    asm volatile(
                        "mma.sync.aligned.m16n8k16.row.col.f32.bf16.bf16.f32 "
                        "{%0,%1,%2,%3}, {%4,%5,%6,%7}, {%8,%9}, {%0,%1,%2,%3};"
                        : "+f"(acc[s][mi][nj][0]), "+f"(acc[s][mi][nj][1]),
                          "+f"(acc[s][mi][nj][2]), "+f"(acc[s][mi][nj][3])
                        : "r"(a[mi][0]), "r"(a[mi][1]),
                          "r"(a[mi][2]), "r"(a[mi][3]),
                          "r"(b[nj][0]), "r"(b[nj][1]));
                }
        }
    };

    // prologue: stages 0,1
    load_A(0, 0); load_B(0, 0); cp_commit();
    load_A(1, 1); load_B(1, 1); cp_commit();

    int cs = 0;   // compute stage = i % 3
    for (int i = 0; i < KCH; i++) {
        cp_wait<1>();      // chunk i resident (chunk i+1 may be in flight)
        __syncthreads();

        const uint32_t As = base + cs * STG;
        const uint32_t Bs = As + ASTG;

        const int ci = i + 2;
        int ls = cs + 2; if (ls >= 3) ls -= 3;   // (i+2) % 3
        const bool more = (ci < KCH);

        // interleave next-chunk load issue with the first two k-steps
        do_kstep(As, Bs, 0);
        if (more) load_A(ci, ls);
        do_kstep(As, Bs, 32);
        if (more) load_B(ci, ls);
        cp_commit();

        do_kstep(As, Bs, 64);
        do_kstep(As, Bs, 96);

        cs++; if (cs == 3) cs = 0;
    }

    // ---------- fused statistics epilogue ----------
    const int colBase = bV * BN + wn + 2 * (lane & 3);
    #pragma unroll
    for (int mi = 0; mi < 2; mi++) {
        #pragma unroll
        for (int r8 = 0; r8 < 2; r8++) {
            int lrow = wm + mi * 16 + r8 * 8 + (lane >> 2);  // 0..63
            int tcol = sTgt[lrow];
            float Sz = 0.f, Sm = 0.f, T = 0.f;
            float vz = -INFINITY, vm = -INFINITY;
            int iz = 0x7FFFFFFF, im = 0x7FFFFFFF;
            #pragma unroll
            for (int nj = 0; nj < 4; nj++) {
                #pragma unroll
                for (int c = 0; c < 2; c++) {
                    float z = acc[0][mi][nj][r8 * 2 + c];
                    float m = acc[1][mi][nj][r8 * 2 + c];
                    int col = colBase + nj * 8 + c;
                    float ez = __expf(z);
                    Sz += ez;
                    Sm += __expf(m);
                    T += ez * (z - m);
                    if (z > vz || (z == vz && col < iz)) { vz = z; iz = col; }
                    if (m > vm || (m == vm && col < im)) { vm = m; im = col; }
                    if (col == tcol) {
                        g_zt[tok0 + lrow] = z;
                        g_mt[tok0 + lrow] = m;
                    }
                }
            }
            #pragma unroll
            for (int d = 1; d < 4; d <<= 1) {
                Sz += __shfl_xor_sync(0xffffffff, Sz, d);
                Sm += __shfl_xor_sync(0xffffffff, Sm, d);
                T  += __shfl_xor_sync(0xffffffff, T, d);
                float ov = __shfl_xor_sync(0xffffffff, vz, d);
                int   oi = __shfl_xor_sync(0xffffffff, iz, d);
                if (ov > vz || (ov == vz && oi < iz)) { vz = ov; iz = oi; }
                float ow = __shfl_xor_sync(0xffffffff, vm, d);
                int   oj = __shfl_xor_sync(0xffffffff, im, d);
                if (ow > vm || (ow == vm && oj < im)) { vm = ow; im = oj; }
            }
            if ((lane & 3) == 0) {
                pSz[lrow][wnG] = Sz; pSm[lrow][wnG] = Sm; pT[lrow][wnG] = T;
                pVz[lrow][wnG] = vz; pIz[lrow][wnG] = iz;
                pVm[lrow][wnG] = vm; pIm[lrow][wnG] = im;
            }
        }
    }
    __syncthreads();

    if (tid < BMT) {
        float Sz = 0.f, Sm = 0.f, T = 0.f;
        float vz = -INFINITY, vm = -INFINITY;
        int iz = 0x7FFFFFFF, im = 0x7FFFFFFF;
        #pragma unroll
        for (int g = 0; g < 4; g++) {
            Sz += pSz[tid][g]; Sm += pSm[tid][g]; T += pT[tid][g];
            float a = pVz[tid][g]; int b = pIz[tid][g];
            if (a > vz || (a == vz && b < iz)) { vz = a; iz = b; }
            float c = pVm[tid][g]; int d = pIm[tid][g];
            if (c > vm || (c == vm && d < im)) { vm = c; im = d; }
        }
        size_t p = (size_t)(tok0 + tid) * NBV + bV;
        g_pSz[p] = Sz; g_pSm[p] = Sm; g_pT[p] = T;
        g_pVz[p] = vz; g_pIz[p] = iz;
        g_pVm[p] = vm; g_pIm[p] = im;
    }
}

// ============================================================
// 3) Per-token reduction over NBV=250 partials -> g_tok
// ============================================================
__global__ __launch_bounds__(256) void reduce_part(const int* __restrict__ tgt) {
    const int n = blockIdx.x;
    const int t = threadIdx.x;

    float Sz = 0.f, Sm = 0.f, T = 0.f;
    float vz = -INFINITY, vm = -INFINITY;
    int iz = 0x7FFFFFFF, im = 0x7FFFFFFF;
    if (t < NBV) {
        size_t p = (size_t)n * NBV + t;
        Sz = g_pSz[p]; Sm = g_pSm[p]; T = g_pT[p];
        vz = g_pVz[p]; iz = g_pIz[p];
        vm = g_pVm[p]; im = g_pIm[p];
    }

    __shared__ float sSz[256], sSm[256], sT[256], sVz[256], sVm[256];
    __shared__ int   sIz[256], sIm[256];
    sSz[t] = Sz; sSm[t] = Sm; sT[t] = T;
    sVz[t] = vz; sIz[t] = iz; sVm[t] = vm; sIm[t] = im;
    __syncthreads();
    for (int s = 128; s; s >>= 1) {
        if (t < s) {
            sSz[t] += sSz[t + s]; sSm[t] += sSm[t + s]; sT[t] += sT[t + s];
            float a = sVz[t + s]; int b = sIz[t + s];
            if (a > sVz[t] || (a == sVz[t] && b < sIz[t])) { sVz[t] = a; sIz[t] = b; }
            float c = sVm[t + s]; int d = sIm[t + s];
            if (c > sVm[t] || (c == sVm[t] && d < sIm[t])) { sVm[t] = c; sIm[t] = d; }
        }
        __syncthreads();
    }

    if (t == 0) {
        long long tg = read_target(tgt, n);
        bool valid = (tg != -100LL);
        float zt = g_zt[n], mt = g_mt[n];
        float logZ = logf(sSz[0]);
        float logM = logf(sSm[0]);
        float ce  = valid ? (logZ - zt) : 0.f;
        float mce = valid ? (logM - mt) : 0.f;
        float kl  = valid ? (sT[0] / sSz[0] - logZ + logM) : 0.f;
        float ag  = (valid && sIz[0] == sIm[0]) ? 1.f : 0.f;
        g_tok[n * 5 + 0] = ce;
        g_tok[n * 5 + 1] = mce;
        g_tok[n * 5 + 2] = kl;
        g_tok[n * 5 + 3] = ag;
        g_tok[n * 5 + 4] = valid ? 1.f : 0.f;
    }
}

// ============================================================
// 4) Final deterministic reduction over tokens -> 5 scalars
// ============================================================
__global__ __launch_bounds__(256) void finalize(float* __restrict__ out) {
    __shared__ float sh[256];
    const int tid = threadIdx.x;
    float s0 = 0, s1 = 0, s2 = 0, s3 = 0, s4 = 0;
    for (int n = tid; n < NTOK; n += 256) {
        s0 += g_tok[n * 5 + 0];
        s1 += g_tok[n * 5 + 1];
        s2 += g_tok[n * 5 + 2];
        s3 += g_tok[n * 5 + 3];
        s4 += g_tok[n * 5 + 4];
    }
    __shared__ float r[5];
    float vals[5] = {s0, s1, s2, s3, s4};
    #pragma unroll
    for (int q = 0; q < 5; q++) {
        sh[tid] = vals[q]; __syncthreads();
        for (int s = 128; s; s >>= 1) { if (tid < s) sh[tid] += sh[tid + s]; __syncthreads(); }
        if (tid == 0) r[q] = sh[0];
        __syncthreads();
    }
    if (tid == 0) {
        float nv = r[4];
        out[0] = (r[0] + 1.0f * r[2]) / nv;
        out[1] = r[0] / nv;
        out[2] = r[1] / nv;
        out[3] = r[2] / nv;
        out[4] = r[3] / nv;
    }
}

// ============================================================
extern "C" void kernel_launch(void* const* d_in, const int* in_sizes, int n_in,
                              void* d_out, int out_size) {
    const float* h   = (const float*)d_in[0];
    const float* mh  = (const float*)d_in[1];
    const float* W   = (const float*)d_in[2];
    const int*   tgt = (const int*)d_in[3];
    float* out = (float*)d_out;

    const int nW8 = VOC * DIM / 8;
    const int nA8 = NTOK * DIM / 8;
    const int total8 = nW8 + 2 * nA8;
    cvt_all<<<(total8 + 255) / 256, 256>>>(h, mh, W);

    cudaFuncSetAttribute(gemm_fused, cudaFuncAttributeMaxDynamicSharedMemorySize,
                         SMEM_TOTAL);
    dim3 gg(NTOK / BMT, NBV);
    gemm_fused<<<gg, 256, SMEM_TOTAL>>>(tgt);

    reduce_part<<<NTOK, 256>>>(tgt);
    finalize<<<1, 256>>>(out);
}

// round 13
// speedup vs baseline: 1.0117x; 1.0117x over previous
#include <cuda_runtime.h>
#include <cuda_bf16.h>
#include <math.h>
#include <stdint.h>

// Problem constants (B=2, S=2048 -> N=4096 tokens; D=2048; V=32000)
#define NTOK 4096
#define DIM  2048
#define VOC  32000

// Fused GEMM tile config: occupancy-2 variant.
// CTA: z AND m for BMT tokens x BN vocab cols, 256 threads, 3 stages.
#define BMT 64                 // tokens per CTA (both streams)
#define BN 128
#define BK 64                  // bf16 elems per K-chunk (128B = SW128 atom row)
#define KCH (DIM / BK)         // 32
#define STAGES 3
#define ASTG (128 * BK * 2)    // 2 streams x 64 rows x 128B = 16384 B
#define BSTG (BN * BK * 2)     // 16384 B
#define STG (ASTG + BSTG)      // 32768 B
#define SMEM_TOTAL (STAGES * STG + 1024)   // ~99 KB -> 2 CTAs/SM
#define NBV (VOC / BN)         // 250 vocab blocks

// ---- scratch (allocation-free: __device__ globals) ----
__device__ __align__(128) __nv_bfloat16 g_Wb[(size_t)VOC * DIM];        // 131 MB
__device__ __align__(128) __nv_bfloat16 g_Ab[(size_t)2 * NTOK * DIM];   // 33.5 MB
// per-(token, vocab-block) partials
__device__ float g_pSz[NTOK * NBV];
__device__ float g_pSm[NTOK * NBV];
__device__ float g_pT [NTOK * NBV];
__device__ float g_pVz[NTOK * NBV];
__device__ float g_pVm[NTOK * NBV];
__device__ int   g_pIz[NTOK * NBV];
__device__ int   g_pIm[NTOK * NBV];
__device__ float g_zt[NTOK];   // target logit (z stream)
__device__ float g_mt[NTOK];   // target logit (m stream)
__device__ float g_tok[NTOK * 5];

// ============================================================
// 1) fp32 -> bf16 conversion (8 floats / thread)
// ============================================================
__global__ void cvt_all(const float* __restrict__ h,
                        const float* __restrict__ mh,
                        const float* __restrict__ W) {
    const int nW8 = VOC * DIM / 8;       // 8,192,000
    const int nA8 = NTOK * DIM / 8;      // 1,048,576
    int i = blockIdx.x * blockDim.x + threadIdx.x;
    const float4* src;
    uint4* dst;
    int j;
    if (i < nW8) {
        src = (const float4*)W; dst = (uint4*)g_Wb; j = i;
    } else if (i < nW8 + nA8) {
        src = (const float4*)h; dst = (uint4*)g_Ab; j = i - nW8;
    } else if (i < nW8 + 2 * nA8) {
        src = (const float4*)mh;
        dst = (uint4*)(g_Ab + (size_t)NTOK * DIM);
        j = i - nW8 - nA8;
    } else {
        return;
    }
    float4 v0 = src[2 * j];
    float4 v1 = src[2 * j + 1];
    __nv_bfloat162 b0 = __floats2bfloat162_rn(v0.x, v0.y);
    __nv_bfloat162 b1 = __floats2bfloat162_rn(v0.z, v0.w);
    __nv_bfloat162 b2 = __floats2bfloat162_rn(v1.x, v1.y);
    __nv_bfloat162 b3 = __floats2bfloat162_rn(v1.z, v1.w);
    uint4 o;
    o.x = *reinterpret_cast<uint32_t*>(&b0);
    o.y = *reinterpret_cast<uint32_t*>(&b1);
    o.z = *reinterpret_cast<uint32_t*>(&b2);
    o.w = *reinterpret_cast<uint32_t*>(&b3);
    dst[j] = o;
}

// ============================================================
// helpers
// ============================================================
static __device__ __forceinline__ uint32_t smem_u32(const void* p) {
    return (uint32_t)__cvta_generic_to_shared(p);
}
static __device__ __forceinline__ void cp16(uint32_t s, const void* g) {
    asm volatile("cp.async.cg.shared.global [%0], [%1], 16;" :: "r"(s), "l"(g));
}
static __device__ __forceinline__ void cp_commit() {
    asm volatile("cp.async.commit_group;" ::: "memory");
}
template <int N>
static __device__ __forceinline__ void cp_wait() {
    asm volatile("cp.async.wait_group %0;" :: "n"(N) : "memory");
}
#define SW128(o) ((o) ^ (((o) >> 3) & 0x70))

// Robust target read (int64 vs int32 autodetect, never OOB)
__device__ __forceinline__ long long read_target(const int* p, int n) {
    int w1 = p[1], w3 = p[3], w5 = p[5], w7 = p[7];
    bool is64 = ((w1 == 0 || w1 == -1) && (w3 == 0 || w3 == -1) &&
                 (w5 == 0 || w5 == -1) && (w7 == 0 || w7 == -1));
    if (is64) {
        long long lo = (unsigned int)p[2 * n];
        long long hi = p[2 * n + 1];
        return (hi << 32) | lo;
    }
    return (long long)p[n];
}

// ============================================================
// 2) FUSED GEMM + softmax statistics, 2 CTAs/SM.
//    CTA: z and m for 64 tokens x 128 vocab cols; 8 warps = 2M x 4N.
//    Mainloop order: kstep0 -> issue next-chunk loads -> ksteps 1..3
//    (load-issue slots hidden under the tensor-pipe drain).
// ============================================================
__global__ void __launch_bounds__(256, 2) gemm_fused(const int* __restrict__ tgt) {
    extern __shared__ __align__(16) char dyn[];
    __shared__ int   sTgt[BMT];
    __shared__ float pSz[BMT][4], pSm[BMT][4], pT[BMT][4];
    __shared__ float pVz[BMT][4], pVm[BMT][4];
    __shared__ int   pIz[BMT][4], pIm[BMT][4];

    const int bT = blockIdx.x, bV = blockIdx.y;
    const int tid = threadIdx.x, wid = tid >> 5, lane = tid & 31;
    const int wm = (wid & 1) * 32;    // token offset within CTA (2 groups)
    const int wnG = wid >> 1;         // N group 0..3
    const int wn = wnG * 32;
    const int tok0 = bT * BMT;

    uint32_t base = smem_u32(dyn);
    base = (base + 1023u) & ~1023u;

    const __nv_bfloat16* __restrict__ Agz = g_Ab + (size_t)tok0 * DIM;
    const __nv_bfloat16* __restrict__ Agm =
        g_Ab + (size_t)NTOK * DIM + (size_t)tok0 * DIM;
    const __nv_bfloat16* __restrict__ Bg = g_Wb + (size_t)(bV * BN) * DIM;

    if (tid < BMT) {
        long long t = read_target(tgt, tok0 + tid);
        int ti = (t != -100LL) ? (int)t : 0;
        sTgt[tid] = min(max(ti, 0), VOC - 1);
    }

    float acc[2][2][4][4];
    #pragma unroll
    for (int s = 0; s < 2; s++)
        #pragma unroll
        for (int i = 0; i < 2; i++)
            #pragma unroll
            for (int j = 0; j < 4; j++)
                #pragma unroll
                for (int k = 0; k < 4; k++) acc[s][i][j][k] = 0.f;

    // async load of one K-chunk into stage st (8 x 16B per thread)
    auto load_chunk = [&](int ci, int st) {
        uint32_t As = base + st * STG;
        uint32_t Bs = As + ASTG;
        #pragma unroll
        for (int r = 0; r < 4; r++) {           // A: 128 rows x 8 segs
            int idx = tid + r * 256;
            int row = idx >> 3, seg = idx & 7;
            const __nv_bfloat16* src = (row < 64)
                ? Agz + (size_t)row * DIM + ci * BK + seg * 8
                : Agm + (size_t)(row - 64) * DIM + ci * BK + seg * 8;
            uint32_t off = (uint32_t)(row * 128 + seg * 16);
            cp16(As + SW128(off), src);
        }
        #pragma unroll
        for (int r = 0; r < 4; r++) {           // B: 128 rows x 8 segs
            int idx = tid + r * 256;
            int row = idx >> 3, seg = idx & 7;
            uint32_t off = (uint32_t)(row * 128 + seg * 16);
            cp16(Bs + SW128(off), Bg + (size_t)row * DIM + ci * BK + seg * 8);
        }
    };

    // one K=16 sub-step: B frags (2 x ldmatrix.x4), per-stream A frags + HMMA
    auto do_kstep = [&](uint32_t As, uint32_t Bs, int kb) {
        uint32_t b[4][2];
        #pragma unroll
        for (int p = 0; p < 2; p++) {
            int row = wn + p * 16 + ((lane >> 4) & 1) * 8 + (lane & 7);
            uint32_t off = (uint32_t)(row * 128 + kb + ((lane >> 3) & 1) * 16);
            uint32_t sb = Bs + SW128(off);
            asm volatile(
                "ldmatrix.sync.aligned.m8n8.x4.shared.b16 {%0,%1,%2,%3}, [%4];"
                : "=r"(b[2 * p][0]), "=r"(b[2 * p][1]),
                  "=r"(b[2 * p + 1][0]), "=r"(b[2 * p + 1][1])
                : "r"(sb));
        }
        #pragma unroll
        for (int s = 0; s < 2; s++) {
            uint32_t a[2][4];
            #pragma unroll
            for (int mi = 0; mi < 2; mi++) {
                int row = s * 64 + wm + mi * 16
                        + ((lane >> 3) & 1) * 8 + (lane & 7);
                uint32_t off = (uint32_t)(row * 128 + kb + (lane >> 4) * 16);
                uint32_t sa = As + SW128(off);
                asm volatile(
                    "ldmatrix.sync.aligned.m8n8.x4.shared.b16 {%0,%1,%2,%3}, [%4];"
                    : "=r"(a[mi][0]), "=r"(a[mi][1]),
                      "=r"(a[mi][2]), "=r"(a[mi][3])
                    : "r"(sa));
            }
            #pragma unroll
            for (int mi = 0; mi < 2; mi++)
                #pragma unroll
                for (int nj = 0; nj < 4; nj++) {
                    asm volatile(
                        "mma.sync.aligned.m16n8k16.row.col.f32.bf16.bf16.f32 "
                        "{%0,%1,%2,%3}, {%4,%5,%6,%7}, {%8,%9}, {%0,%1,%2,%3};"
                        : "+f"(acc[s][mi][nj][0]), "+f"(acc[s][mi][nj][1]),
                          "+f"(acc[s][mi][nj][2]), "+f"(acc[s][mi][nj][3])
                        : "r"(a[mi][0]), "r"(a[mi][1]),
                          "r"(a[mi][2]), "r"(a[mi][3]),
                          "r"(b[nj][0]), "r"(b[nj][1]));
                }
        }
    };

    // prologue: stages 0,1
    load_chunk(0, 0); cp_commit();
    load_chunk(1, 1); cp_commit();

    int cs = 0;   // compute stage = i % 3
    for (int i = 0; i < KCH; i++) {
        cp_wait<1>();      // chunk i resident (chunk i+1 may be in flight)
        __syncthreads();

        const uint32_t As = base + cs * STG;
        const uint32_t Bs = As + ASTG;

        // kstep 0 first: start the tensor pipe before burning issue
        // slots on next-chunk LDGSTS.
        do_kstep(As, Bs, 0);

        const int ci = i + 2;
        if (ci < KCH) {
            int ls = cs + 2; if (ls >= 3) ls -= 3;   // (i+2) % 3
            load_chunk(ci, ls);
        }
        cp_commit();

        do_kstep(As, Bs, 32);
        do_kstep(As, Bs, 64);
        do_kstep(As, Bs, 96);

        cs++; if (cs == 3) cs = 0;
    }

    // ---------- fused statistics epilogue ----------
    const int colBase = bV * BN + wn + 2 * (lane & 3);
    #pragma unroll
    for (int mi = 0; mi < 2; mi++) {
        #pragma unroll
        for (int r8 = 0; r8 < 2; r8++) {
            int lrow = wm + mi * 16 + r8 * 8 + (lane >> 2);  // 0..63
            int tcol = sTgt[lrow];
            float Sz = 0.f, Sm = 0.f, T = 0.f;
            float vz = -INFINITY, vm = -INFINITY;
            int iz = 0x7FFFFFFF, im = 0x7FFFFFFF;
            #pragma unroll
            for (int nj = 0; nj < 4; nj++) {
                #pragma unroll
                for (int c = 0; c < 2; c++) {
                    float z = acc[0][mi][nj][r8 * 2 + c];
                    float m = acc[1][mi][nj][r8 * 2 + c];
                    int col = colBase + nj * 8 + c;
                    float ez = __expf(z);
                    Sz += ez;
                    Sm += __expf(m);
                    T += ez * (z - m);
                    if (z > vz || (z == vz && col < iz)) { vz = z; iz = col; }
                    if (m > vm || (m == vm && col < im)) { vm = m; im = col; }
                    if (col == tcol) {
                        g_zt[tok0 + lrow] = z;
                        g_mt[tok0 + lrow] = m;
                    }
                }
            }
            #pragma unroll
            for (int d = 1; d < 4; d <<= 1) {
                Sz += __shfl_xor_sync(0xffffffff, Sz, d);
                Sm += __shfl_xor_sync(0xffffffff, Sm, d);
                T  += __shfl_xor_sync(0xffffffff, T, d);
                float ov = __shfl_xor_sync(0xffffffff, vz, d);
                int   oi = __shfl_xor_sync(0xffffffff, iz, d);
                if (ov > vz || (ov == vz && oi < iz)) { vz = ov; iz = oi; }
                float ow = __shfl_xor_sync(0xffffffff, vm, d);
                int   oj = __shfl_xor_sync(0xffffffff, im, d);
                if (ow > vm || (ow == vm && oj < im)) { vm = ow; im = oj; }
            }
            if ((lane & 3) == 0) {
                pSz[lrow][wnG] = Sz; pSm[lrow][wnG] = Sm; pT[lrow][wnG] = T;
                pVz[lrow][wnG] = vz; pIz[lrow][wnG] = iz;
                pVm[lrow][wnG] = vm; pIm[lrow][wnG] = im;
            }
        }
    }
    __syncthreads();

    if (tid < BMT) {
        float Sz = 0.f, Sm = 0.f, T = 0.f;
        float vz = -INFINITY, vm = -INFINITY;
        int iz = 0x7FFFFFFF, im = 0x7FFFFFFF;
        #pragma unroll
        for (int g = 0; g < 4; g++) {
            Sz += pSz[tid][g]; Sm += pSm[tid][g]; T += pT[tid][g];
            float a = pVz[tid][g]; int b = pIz[tid][g];
            if (a > vz || (a == vz && b < iz)) { vz = a; iz = b; }
            float c = pVm[tid][g]; int d = pIm[tid][g];
            if (c > vm || (c == vm && d < im)) { vm = c; im = d; }
        }
        size_t p = (size_t)(tok0 + tid) * NBV + bV;
        g_pSz[p] = Sz; g_pSm[p] = Sm; g_pT[p] = T;
        g_pVz[p] = vz; g_pIz[p] = iz;
        g_pVm[p] = vm; g_pIm[p] = im;
    }
}

// ============================================================
// 3) Per-token reduction over NBV=250 partials -> g_tok
// ============================================================
__global__ __launch_bounds__(256) void reduce_part(const int* __restrict__ tgt) {
    const int n = blockIdx.x;
    const int t = threadIdx.x;

    float Sz = 0.f, Sm = 0.f, T = 0.f;
    float vz = -INFINITY, vm = -INFINITY;
    int iz = 0x7FFFFFFF, im = 0x7FFFFFFF;
    if (t < NBV) {
        size_t p = (size_t)n * NBV + t;
        Sz = g_pSz[p]; Sm = g_pSm[p]; T = g_pT[p];
        vz = g_pVz[p]; iz = g_pIz[p];
        vm = g_pVm[p]; im = g_pIm[p];
    }

    __shared__ float sSz[256], sSm[256], sT[256], sVz[256], sVm[256];
    __shared__ int   sIz[256], sIm[256];
    sSz[t] = Sz; sSm[t] = Sm; sT[t] = T;
    sVz[t] = vz; sIz[t] = iz; sVm[t] = vm; sIm[t] = im;
    __syncthreads();
    for (int s = 128; s; s >>= 1) {
        if (t < s) {
            sSz[t] += sSz[t + s]; sSm[t] += sSm[t + s]; sT[t] += sT[t + s];
            float a = sVz[t + s]; int b = sIz[t + s];
            if (a > sVz[t] || (a == sVz[t] && b < sIz[t])) { sVz[t] = a; sIz[t] = b; }
            float c = sVm[t + s]; int d = sIm[t + s];
            if (c > sVm[t] || (c == sVm[t] && d < sIm[t])) { sVm[t] = c; sIm[t] = d; }
        }
        __syncthreads();
    }

    if (t == 0) {
        long long tg = read_target(tgt, n);
        bool valid = (tg != -100LL);
        float zt = g_zt[n], mt = g_mt[n];
        float logZ = logf(sSz[0]);
        float logM = logf(sSm[0]);
        float ce  = valid ? (logZ - zt) : 0.f;
        float mce = valid ? (logM - mt) : 0.f;
        float kl  = valid ? (sT[0] / sSz[0] - logZ + logM) : 0.f;
        float ag  = (valid && sIz[0] == sIm[0]) ? 1.f : 0.f;
        g_tok[n * 5 + 0] = ce;
        g_tok[n * 5 + 1] = mce;
        g_tok[n * 5 + 2] = kl;
        g_tok[n * 5 + 3] = ag;
        g_tok[n * 5 + 4] = valid ? 1.f : 0.f;
    }
}

// ============================================================
// 4) Final deterministic reduction over tokens -> 5 scalars
// ============================================================
__global__ __launch_bounds__(256) void finalize(float* __restrict__ out) {
    __shared__ float sh[256];
    const int tid = threadIdx.x;
    float s0 = 0, s1 = 0, s2 = 0, s3 = 0, s4 = 0;
    for (int n = tid; n < NTOK; n += 256) {
        s0 += g_tok[n * 5 + 0];
        s1 += g_tok[n * 5 + 1];
        s2 += g_tok[n * 5 + 2];
        s3 += g_tok[n * 5 + 3];
        s4 += g_tok[n * 5 + 4];
    }
    __shared__ float r[5];
    float vals[5] = {s0, s1, s2, s3, s4};
    #pragma unroll
    for (int q = 0; q < 5; q++) {
        sh[tid] = vals[q]; __syncthreads();
        for (int s = 128; s; s >>= 1) { if (tid < s) sh[tid] += sh[tid + s]; __syncthreads(); }
        if (tid == 0) r[q] = sh[0];
        __syncthreads();
    }
    if (tid == 0) {
        float nv = r[4];
        out[0] = (r[0] + 1.0f * r[2]) / nv;
        out[1] = r[0] / nv;
        out[2] = r[1] / nv;
        out[3] = r[2] / nv;
        out[4] = r[3] / nv;
    }
}

// ============================================================
extern "C" void kernel_launch(void* const* d_in, const int* in_sizes, int n_in,
                              void* d_out, int out_size) {
    const float* h   = (const float*)d_in[0];
    const float* mh  = (const float*)d_in[1];
    const float* W   = (const float*)d_in[2];
    const int*   tgt = (const int*)d_in[3];
    float* out = (float*)d_out;

    const int nW8 = VOC * DIM / 8;
    const int nA8 = NTOK * DIM / 8;
    const int total8 = nW8 + 2 * nA8;
    cvt_all<<<(total8 + 255) / 256, 256>>>(h, mh, W);

    cudaFuncSetAttribute(gemm_fused, cudaFuncAttributeMaxDynamicSharedMemorySize,
                         SMEM_TOTAL);
    dim3 gg(NTOK / BMT, NBV);
    gemm_fused<<<gg, 256, SMEM_TOTAL>>>(tgt);

    reduce_part<<<NTOK, 256>>>(tgt);
    finalize<<<1, 256>>>(out);
}

// round 14
// speedup vs baseline: 1.0500x; 1.0379x over previous
#include <cuda_runtime.h>
#include <cuda_fp16.h>
#include <math.h>
#include <stdint.h>

// Problem constants (B=2, S=2048 -> N=4096 tokens; D=2048; V=32000)
#define NTOK 4096
#define DIM  2048
#define VOC  32000

// Fused GEMM tile config: occupancy-2 variant, fp16 x fp16 -> fp16 acc.
#define BMT 64                 // tokens per CTA (both streams)
#define BN 128
#define BK 64                  // fp16 elems per K-chunk (128B = SW128 atom row)
#define KCH (DIM / BK)         // 32
#define STAGES 3
#define ASTG (128 * BK * 2)    // 2 streams x 64 rows x 128B = 16384 B
#define BSTG (BN * BK * 2)     // 16384 B
#define STG (ASTG + BSTG)      // 32768 B
#define SMEM_TOTAL (STAGES * STG + 1024)   // ~99 KB -> 2 CTAs/SM
#define NBV (VOC / BN)         // 250 vocab blocks

// ---- scratch (allocation-free: __device__ globals) ----
__device__ __align__(128) __half g_Wb[(size_t)VOC * DIM];        // 131 MB
__device__ __align__(128) __half g_Ab[(size_t)2 * NTOK * DIM];   // 33.5 MB
// per-(token, vocab-block) partials
__device__ float g_pSz[NTOK * NBV];
__device__ float g_pSm[NTOK * NBV];
__device__ float g_pT [NTOK * NBV];
__device__ float g_pVz[NTOK * NBV];
__device__ float g_pVm[NTOK * NBV];
__device__ int   g_pIz[NTOK * NBV];
__device__ int   g_pIm[NTOK * NBV];
__device__ float g_zt[NTOK];   // target logit (z stream)
__device__ float g_mt[NTOK];   // target logit (m stream)
__device__ float g_tok[NTOK * 5];

// ============================================================
// 1) fp32 -> fp16 conversion (8 floats / thread)
// ============================================================
__global__ void cvt_all(const float* __restrict__ h,
                        const float* __restrict__ mh,
                        const float* __restrict__ W) {
    const int nW8 = VOC * DIM / 8;       // 8,192,000
    const int nA8 = NTOK * DIM / 8;      // 1,048,576
    int i = blockIdx.x * blockDim.x + threadIdx.x;
    const float4* src;
    uint4* dst;
    int j;
    if (i < nW8) {
        src = (const float4*)W; dst = (uint4*)g_Wb; j = i;
    } else if (i < nW8 + nA8) {
        src = (const float4*)h; dst = (uint4*)g_Ab; j = i - nW8;
    } else if (i < nW8 + 2 * nA8) {
        src = (const float4*)mh;
        dst = (uint4*)(g_Ab + (size_t)NTOK * DIM);
        j = i - nW8 - nA8;
    } else {
        return;
    }
    float4 v0 = src[2 * j];
    float4 v1 = src[2 * j + 1];
    __half2 b0 = __floats2half2_rn(v0.x, v0.y);
    __half2 b1 = __floats2half2_rn(v0.z, v0.w);
    __half2 b2 = __floats2half2_rn(v1.x, v1.y);
    __half2 b3 = __floats2half2_rn(v1.z, v1.w);
    uint4 o;
    o.x = *reinterpret_cast<uint32_t*>(&b0);
    o.y = *reinterpret_cast<uint32_t*>(&b1);
    o.z = *reinterpret_cast<uint32_t*>(&b2);
    o.w = *reinterpret_cast<uint32_t*>(&b3);
    dst[j] = o;
}

// ============================================================
// helpers
// ============================================================
static __device__ __forceinline__ uint32_t smem_u32(const void* p) {
    return (uint32_t)__cvta_generic_to_shared(p);
}
static __device__ __forceinline__ void cp16(uint32_t s, const void* g) {
    asm volatile("cp.async.cg.shared.global [%0], [%1], 16;" :: "r"(s), "l"(g));
}
static __device__ __forceinline__ void cp_commit() {
    asm volatile("cp.async.commit_group;" ::: "memory");
}
template <int N>
static __device__ __forceinline__ void cp_wait() {
    asm volatile("cp.async.wait_group %0;" :: "n"(N) : "memory");
}
#define SW128(o) ((o) ^ (((o) >> 3) & 0x70))

// Robust target read (int64 vs int32 autodetect, never OOB)
__device__ __forceinline__ long long read_target(const int* p, int n) {
    int w1 = p[1], w3 = p[3], w5 = p[5], w7 = p[7];
    bool is64 = ((w1 == 0 || w1 == -1) && (w3 == 0 || w3 == -1) &&
                 (w5 == 0 || w5 == -1) && (w7 == 0 || w7 == -1));
    if (is64) {
        long long lo = (unsigned int)p[2 * n];
        long long hi = p[2 * n + 1];
        return (hi << 32) | lo;
    }
    return (long long)p[n];
}

// ============================================================
// 2) FUSED GEMM + softmax statistics, 2 CTAs/SM, f16 accumulators.
//    CTA: z and m for 64 tokens x 128 vocab cols; 8 warps = 2M x 4N.
//    D fragment (f16 acc): 2 x b32 regs per tile; reg r8 = row group
//    (row, row+8), packed halves = cols 2*(lane&3), +1.
// ============================================================
__global__ void __launch_bounds__(256, 2) gemm_fused(const int* __restrict__ tgt) {
    extern __shared__ __align__(16) char dyn[];
    __shared__ int   sTgt[BMT];
    __shared__ float pSz[BMT][4], pSm[BMT][4], pT[BMT][4];
    __shared__ float pVz[BMT][4], pVm[BMT][4];
    __shared__ int   pIz[BMT][4], pIm[BMT][4];

    const int bT = blockIdx.x, bV = blockIdx.y;
    const int tid = threadIdx.x, wid = tid >> 5, lane = tid & 31;
    const int wm = (wid & 1) * 32;    // token offset within CTA (2 groups)
    const int wnG = wid >> 1;         // N group 0..3
    const int wn = wnG * 32;
    const int tok0 = bT * BMT;

    uint32_t base = smem_u32(dyn);
    base = (base + 1023u) & ~1023u;

    const __half* __restrict__ Agz = g_Ab + (size_t)tok0 * DIM;
    const __half* __restrict__ Agm =
        g_Ab + (size_t)NTOK * DIM + (size_t)tok0 * DIM;
    const __half* __restrict__ Bg = g_Wb + (size_t)(bV * BN) * DIM;

    if (tid < BMT) {
        long long t = read_target(tgt, tok0 + tid);
        int ti = (t != -100LL) ? (int)t : 0;
        sTgt[tid] = min(max(ti, 0), VOC - 1);
    }

    // f16 accumulators: [stream][mi][nj][r8], each b32 = half2 (c0,c1)
    uint32_t acc[2][2][4][2];
    #pragma unroll
    for (int s = 0; s < 2; s++)
        #pragma unroll
        for (int i = 0; i < 2; i++)
            #pragma unroll
            for (int j = 0; j < 4; j++) {
                acc[s][i][j][0] = 0u;
                acc[s][i][j][1] = 0u;
            }

    // async load of one K-chunk into stage st (8 x 16B per thread)
    auto load_chunk = [&](int ci, int st) {
        uint32_t As = base + st * STG;
        uint32_t Bs = As + ASTG;
        #pragma unroll
        for (int r = 0; r < 4; r++) {           // A: 128 rows x 8 segs
            int idx = tid + r * 256;
            int row = idx >> 3, seg = idx & 7;
            const __half* src = (row < 64)
                ? Agz + (size_t)row * DIM + ci * BK + seg * 8
                : Agm + (size_t)(row - 64) * DIM + ci * BK + seg * 8;
            uint32_t off = (uint32_t)(row * 128 + seg * 16);
            cp16(As + SW128(off), src);
        }
        #pragma unroll
        for (int r = 0; r < 4; r++) {           // B: 128 rows x 8 segs
            int idx = tid + r * 256;
            int row = idx >> 3, seg = idx & 7;
            uint32_t off = (uint32_t)(row * 128 + seg * 16);
            cp16(Bs + SW128(off), Bg + (size_t)row * DIM + ci * BK + seg * 8);
        }
    };

    // one K=16 sub-step: B frags (2 x ldmatrix.x4), per-stream A frags + HMMA
    auto do_kstep = [&](uint32_t As, uint32_t Bs, int kb) {
        uint32_t b[4][2];
        #pragma unroll
        for (int p = 0; p < 2; p++) {
            int row = wn + p * 16 + ((lane >> 4) & 1) * 8 + (lane & 7);
            uint32_t off = (uint32_t)(row * 128 + kb + ((lane >> 3) & 1) * 16);
            uint32_t sb = Bs + SW128(off);
            asm volatile(
                "ldmatrix.sync.aligned.m8n8.x4.shared.b16 {%0,%1,%2,%3}, [%4];"
                : "=r"(b[2 * p][0]), "=r"(b[2 * p][1]),
                  "=r"(b[2 * p + 1][0]), "=r"(b[2 * p + 1][1])
                : "r"(sb));
        }
        #pragma unroll
        for (int s = 0; s < 2; s++) {
            uint32_t a[2][4];
            #pragma unroll
            for (int mi = 0; mi < 2; mi++) {
                int row = s * 64 + wm + mi * 16
                        + ((lane >> 3) & 1) * 8 + (lane & 7);
                uint32_t off = (uint32_t)(row * 128 + kb + (lane >> 4) * 16);
                uint32_t sa = As + SW128(off);
                asm volatile(
                    "ldmatrix.sync.aligned.m8n8.x4.shared.b16 {%0,%1,%2,%3}, [%4];"
                    : "=r"(a[mi][0]), "=r"(a[mi][1]),
                      "=r"(a[mi][2]), "=r"(a[mi][3])
                    : "r"(sa));
            }
            #pragma unroll
            for (int mi = 0; mi < 2; mi++)
                #pragma unroll
                for (int nj = 0; nj < 4; nj++) {
                    asm volatile(
                        "mma.sync.aligned.m16n8k16.row.col.f16.f16.f16.f16 "
                        "{%0,%1}, {%2,%3,%4,%5}, {%6,%7}, {%0,%1};"
                        : "+r"(acc[s][mi][nj][0]), "+r"(acc[s][mi][nj][1])
                        : "r"(a[mi][0]), "r"(a[mi][1]),
                          "r"(a[mi][2]), "r"(a[mi][3]),
                          "r"(b[nj][0]), "r"(b[nj][1]));
                }
        }
    };

    // prologue: stages 0,1
    load_chunk(0, 0); cp_commit();
    load_chunk(1, 1); cp_commit();

    int cs = 0;   // compute stage = i % 3
    for (int i = 0; i < KCH; i++) {
        cp_wait<1>();      // chunk i resident (chunk i+1 may be in flight)
        __syncthreads();

        const uint32_t As = base + cs * STG;
        const uint32_t Bs = As + ASTG;

        // kstep 0 first: start the tensor pipe before burning issue
        // slots on next-chunk LDGSTS.
        do_kstep(As, Bs, 0);

        const int ci = i + 2;
        if (ci < KCH) {
            int ls = cs + 2; if (ls >= 3) ls -= 3;   // (i+2) % 3
            load_chunk(ci, ls);
        }
        cp_commit();

        do_kstep(As, Bs, 32);
        do_kstep(As, Bs, 64);
        do_kstep(As, Bs, 96);

        cs++; if (cs == 3) cs = 0;
    }

    // ---------- fused statistics epilogue ----------
    const int colBase = bV * BN + wn + 2 * (lane & 3);
    #pragma unroll
    for (int mi = 0; mi < 2; mi++) {
        #pragma unroll
        for (int r8 = 0; r8 < 2; r8++) {
            int lrow = wm + mi * 16 + r8 * 8 + (lane >> 2);  // 0..63
            int tcol = sTgt[lrow];
            float Sz = 0.f, Sm = 0.f, T = 0.f;
            float vz = -INFINITY, vm = -INFINITY;
            int iz = 0x7FFFFFFF, im = 0x7FFFFFFF;
            #pragma unroll
            for (int nj = 0; nj < 4; nj++) {
                __half2 hz = *reinterpret_cast<__half2*>(&acc[0][mi][nj][r8]);
                __half2 hm = *reinterpret_cast<__half2*>(&acc[1][mi][nj][r8]);
                float zc[2] = {__low2float(hz), __high2float(hz)};
                float mc[2] = {__low2float(hm), __high2float(hm)};
                #pragma unroll
                for (int c = 0; c < 2; c++) {
                    float z = zc[c];
                    float m = mc[c];
                    int col = colBase + nj * 8 + c;
                    float ez = __expf(z);
                    Sz += ez;
                    Sm += __expf(m);
                    T += ez * (z - m);
                    if (z > vz || (z == vz && col < iz)) { vz = z; iz = col; }
                    if (m > vm || (m == vm && col < im)) { vm = m; im = col; }
                    if (col == tcol) {
                        g_zt[tok0 + lrow] = z;
                        g_mt[tok0 + lrow] = m;
                    }
                }
            }
            #pragma unroll
            for (int d = 1; d < 4; d <<= 1) {
                Sz += __shfl_xor_sync(0xffffffff, Sz, d);
                Sm += __shfl_xor_sync(0xffffffff, Sm, d);
                T  += __shfl_xor_sync(0xffffffff, T, d);
                float ov = __shfl_xor_sync(0xffffffff, vz, d);
                int   oi = __shfl_xor_sync(0xffffffff, iz, d);
                if (ov > vz || (ov == vz && oi < iz)) { vz = ov; iz = oi; }
                float ow = __shfl_xor_sync(0xffffffff, vm, d);
                int   oj = __shfl_xor_sync(0xffffffff, im, d);
                if (ow > vm || (ow == vm && oj < im)) { vm = ow; im = oj; }
            }
            if ((lane & 3) == 0) {
                pSz[lrow][wnG] = Sz; pSm[lrow][wnG] = Sm; pT[lrow][wnG] = T;
                pVz[lrow][wnG] = vz; pIz[lrow][wnG] = iz;
                pVm[lrow][wnG] = vm; pIm[lrow][wnG] = im;
            }
        }
    }
    __syncthreads();

    if (tid < BMT) {
        float Sz = 0.f, Sm = 0.f, T = 0.f;
        float vz = -INFINITY, vm = -INFINITY;
        int iz = 0x7FFFFFFF, im = 0x7FFFFFFF;
        #pragma unroll
        for (int g = 0; g < 4; g++) {
            Sz += pSz[tid][g]; Sm += pSm[tid][g]; T += pT[tid][g];
            float a = pVz[tid][g]; int b = pIz[tid][g];
            if (a > vz || (a == vz && b < iz)) { vz = a; iz = b; }
            float c = pVm[tid][g]; int d = pIm[tid][g];
            if (c > vm || (c == vm && d < im)) { vm = c; im = d; }
        }
        size_t p = (size_t)(tok0 + tid) * NBV + bV;
        g_pSz[p] = Sz; g_pSm[p] = Sm; g_pT[p] = T;
        g_pVz[p] = vz; g_pIz[p] = iz;
        g_pVm[p] = vm; g_pIm[p] = im;
    }
}

// ============================================================
// 3) Per-token reduction over NBV=250 partials -> g_tok
// ============================================================
__global__ __launch_bounds__(256) void reduce_part(const int* __restrict__ tgt) {
    const int n = blockIdx.x;
    const int t = threadIdx.x;

    float Sz = 0.f, Sm = 0.f, T = 0.f;
    float vz = -INFINITY, vm = -INFINITY;
    int iz = 0x7FFFFFFF, im = 0x7FFFFFFF;
    if (t < NBV) {
        size_t p = (size_t)n * NBV + t;
        Sz = g_pSz[p]; Sm = g_pSm[p]; T = g_pT[p];
        vz = g_pVz[p]; iz = g_pIz[p];
        vm = g_pVm[p]; im = g_pIm[p];
    }

    __shared__ float sSz[256], sSm[256], sT[256], sVz[256], sVm[256];
    __shared__ int   sIz[256], sIm[256];
    sSz[t] = Sz; sSm[t] = Sm; sT[t] = T;
    sVz[t] = vz; sIz[t] = iz; sVm[t] = vm; sIm[t] = im;
    __syncthreads();
    for (int s = 128; s; s >>= 1) {
        if (t < s) {
            sSz[t] += sSz[t + s]; sSm[t] += sSm[t + s]; sT[t] += sT[t + s];
            float a = sVz[t + s]; int b = sIz[t + s];
            if (a > sVz[t] || (a == sVz[t] && b < sIz[t])) { sVz[t] = a; sIz[t] = b; }
            float c = sVm[t + s]; int d = sIm[t + s];
            if (c > sVm[t] || (c == sVm[t] && d < sIm[t])) { sVm[t] = c; sIm[t] = d; }
        }
        __syncthreads();
    }

    if (t == 0) {
        long long tg = read_target(tgt, n);
        bool valid = (tg != -100LL);
        float zt = g_zt[n], mt = g_mt[n];
        float logZ = logf(sSz[0]);
        float logM = logf(sSm[0]);
        float ce  = valid ? (logZ - zt) : 0.f;
        float mce = valid ? (logM - mt) : 0.f;
        float kl  = valid ? (sT[0] / sSz[0] - logZ + logM) : 0.f;
        float ag  = (valid && sIz[0] == sIm[0]) ? 1.f : 0.f;
        g_tok[n * 5 + 0] = ce;
        g_tok[n * 5 + 1] = mce;
        g_tok[n * 5 + 2] = kl;
        g_tok[n * 5 + 3] = ag;
        g_tok[n * 5 + 4] = valid ? 1.f : 0.f;
    }
}

// ============================================================
// 4) Final deterministic reduction over tokens -> 5 scalars
// ============================================================
__global__ __launch_bounds__(256) void finalize(float* __restrict__ out) {
    __shared__ float sh[256];
    const int tid = threadIdx.x;
    float s0 = 0, s1 = 0, s2 = 0, s3 = 0, s4 = 0;
    for (int n = tid; n < NTOK; n += 256) {
        s0 += g_tok[n * 5 + 0];
        s1 += g_tok[n * 5 + 1];
        s2 += g_tok[n * 5 + 2];
        s3 += g_tok[n * 5 + 3];
        s4 += g_tok[n * 5 + 4];
    }
    __shared__ float r[5];
    float vals[5] = {s0, s1, s2, s3, s4};
    #pragma unroll
    for (int q = 0; q < 5; q++) {
        sh[tid] = vals[q]; __syncthreads();
        for (int s = 128; s; s >>= 1) { if (tid < s) sh[tid] += sh[tid + s]; __syncthreads(); }
        if (tid == 0) r[q] = sh[0];
        __syncthreads();
    }
    if (tid == 0) {
        float nv = r[4];
        out[0] = (r[0] + 1.0f * r[2]) / nv;
        out[1] = r[0] / nv;
        out[2] = r[1] / nv;
        out[3] = r[2] / nv;
        out[4] = r[3] / nv;
    }
}

// ============================================================
extern "C" void kernel_launch(void* const* d_in, const int* in_sizes, int n_in,
                              void* d_out, int out_size) {
    const float* h   = (const float*)d_in[0];
    const float* mh  = (const float*)d_in[1];
    const float* W   = (const float*)d_in[2];
    const int*   tgt = (const int*)d_in[3];
    float* out = (float*)d_out;

    const int nW8 = VOC * DIM / 8;
    const int nA8 = NTOK * DIM / 8;
    const int total8 = nW8 + 2 * nA8;
    cvt_all<<<(total8 + 255) / 256, 256>>>(h, mh, W);

    cudaFuncSetAttribute(gemm_fused, cudaFuncAttributeMaxDynamicSharedMemorySize,
                         SMEM_TOTAL);
    dim3 gg(NTOK / BMT, NBV);
    gemm_fused<<<gg, 256, SMEM_TOTAL>>>(tgt);

    reduce_part<<<NTOK, 256>>>(tgt);
    finalize<<<1, 256>>>(out);
}